// round 1
// baseline (speedup 1.0000x reference)
#include <cuda_runtime.h>
#include <cstdint>
#include <math.h>

// Problem constants
#define NN   100000
#define NCAT 20
#define EMBD 32
#define CARD 100

// ---------------- scratch (device globals; no allocation allowed) ----------------
__device__ float g_h1[(size_t)NN * 128];   // MLP hidden 1 / later conv2 output (x3)
__device__ float g_h2[(size_t)NN * 128];   // MLP hidden 2
__device__ float g_x [(size_t)NN * 192];   // concat(h, x_cont)
__device__ float g_y [(size_t)NN * 128];   // x @ Wl per conv
__device__ float g_agg[(size_t)NN * 128];  // edge-aggregated y
__device__ float g_x2[(size_t)NN * 128];   // conv1 output
__device__ float g_deg[NN];
__device__ float g_s1[NN];                 // conv3: dot(x, Wl)
__device__ float g_s2[NN];                 // conv3: dot(x, Wr)
__device__ float g_aggs[NN];               // conv3 scalar aggregation

__device__ __forceinline__ float gelu_f(float v) {
    return 0.5f * v * (1.0f + erff(v * 0.70710678118654752f));
}

// ---------------- zero kernel (float4 grid-stride) ----------------
__global__ void zero_kernel(float* __restrict__ p, int n4) {
    int i = blockIdx.x * blockDim.x + threadIdx.x;
    int stride = gridDim.x * blockDim.x;
    float4* p4 = (float4*)p;
    float4 z = make_float4(0.f, 0.f, 0.f, 0.f);
    for (; i < n4; i += stride) p4[i] = z;
}

// ---------------- generic SIMT GEMM: [M x K] @ [K x 128] ----------------
// INMODE: 0 = read A[m*K+k], 1 = embedding gather (A unused)
// EPI:    0 = gelu(acc + bias)
//         1 = acc + bias (bias may be null)
//         2 = gelu(acc + bias + g_agg[m]/max(deg,1))
template<int K, int INMODE, int EPI>
__global__ __launch_bounds__(256)
void gemm_kernel(const float* __restrict__ A,
                 const float* __restrict__ W,
                 const float* __restrict__ bias,
                 float* __restrict__ C, int ldc,
                 const int* __restrict__ xcat,
                 const float* __restrict__ emb)
{
    __shared__ __align__(16) float As[16 * 132];  // [k][m], pad 4 (528B row = 33*16B)
    __shared__ __align__(16) float Bs[16 * 128];  // [k][n]

    const int tid = threadIdx.x;
    const int m0  = blockIdx.x * 128;
    const int tr  = tid >> 4;        // 0..15
    const int tc  = tid & 15;        // 0..15
    const int row = tr * 8;
    const int col = tc * 8;

    float acc[8][8];
#pragma unroll
    for (int i = 0; i < 8; i++)
#pragma unroll
        for (int j = 0; j < 8; j++) acc[i][j] = 0.f;

    for (int k0 = 0; k0 < K; k0 += 16) {
        __syncthreads();
        // Load A tile (128 rows x 16 k), store transposed As[k][m]
#pragma unroll
        for (int i = 0; i < 8; i++) {
            int flat = tid + i * 256;
            int m = flat >> 4;
            int k = flat & 15;
            int gm = m0 + m;
            float v = 0.f;
            if (gm < NN) {
                int gk = k0 + k;
                if (INMODE == 1) {
                    int c = gk >> 5, d = gk & 31;
                    int cat = xcat[gm * NCAT + c];
                    v = emb[(c * CARD + cat) * EMBD + d];
                } else {
                    v = A[gm * K + gk];
                }
            }
            As[k * 132 + m] = v;
        }
        // Load B tile (16 k x 128 n)
#pragma unroll
        for (int i = 0; i < 8; i++) {
            int flat = tid + i * 256;
            int n = flat & 127;
            int k = flat >> 7;
            Bs[k * 128 + n] = W[(k0 + k) * 128 + n];
        }
        __syncthreads();

#pragma unroll
        for (int kk = 0; kk < 16; kk++) {
            float4 a0 = *(const float4*)&As[kk * 132 + row];
            float4 a1 = *(const float4*)&As[kk * 132 + row + 4];
            float4 b0 = *(const float4*)&Bs[kk * 128 + col];
            float4 b1 = *(const float4*)&Bs[kk * 128 + col + 4];
            float ar[8] = {a0.x, a0.y, a0.z, a0.w, a1.x, a1.y, a1.z, a1.w};
            float br[8] = {b0.x, b0.y, b0.z, b0.w, b1.x, b1.y, b1.z, b1.w};
#pragma unroll
            for (int i = 0; i < 8; i++)
#pragma unroll
                for (int j = 0; j < 8; j++)
                    acc[i][j] += ar[i] * br[j];
        }
    }

    // bias fragment
    float bv[8];
#pragma unroll
    for (int j = 0; j < 8; j++) bv[j] = bias ? bias[col + j] : 0.f;

#pragma unroll
    for (int i = 0; i < 8; i++) {
        int m = m0 + row + i;
        if (m < NN) {
            float inv = 1.f;
            if (EPI == 2) inv = 1.f / fmaxf(g_deg[m], 1.f);
#pragma unroll
            for (int j = 0; j < 8; j++) {
                float v = acc[i][j] + bv[j];
                if (EPI == 2) v += g_agg[(size_t)m * 128 + col + j] * inv;
                if (EPI == 0 || EPI == 2) v = gelu_f(v);
                C[(size_t)m * ldc + col + j] = v;
            }
        }
    }
}

// ---------------- degree computation ----------------
__global__ void deg_kernel(const int* __restrict__ ei, int E) {
    int e = blockIdx.x * blockDim.x + threadIdx.x;
    if (e < E) atomicAdd(&g_deg[ei[E + e]], 1.0f);
}

// ---------------- 128-wide edge scatter: g_agg[dst] += y[src] ----------------
// one warp per edge; lane handles float4 (32 lanes * 4 = 128)
__global__ void scatter_vec(const float* __restrict__ y, const int* __restrict__ ei, int E) {
    int g = blockIdx.x * blockDim.x + threadIdx.x;
    int e = g >> 5;
    if (e >= E) return;
    int lane = g & 31;
    int src = __ldg(&ei[e]);
    int dst = __ldg(&ei[E + e]);
    float4 v = *(const float4*)&y[(size_t)src * 128 + lane * 4];
    float* p = &g_agg[(size_t)dst * 128 + lane * 4];
    asm volatile("red.global.add.v4.f32 [%0], {%1,%2,%3,%4};"
                 :: "l"(p), "f"(v.x), "f"(v.y), "f"(v.z), "f"(v.w) : "memory");
}

// ---------------- conv3: per-node dots with Wl/Wr columns ----------------
__global__ void conv3_dot(const float* __restrict__ Wl, const float* __restrict__ Wr) {
    int g = blockIdx.x * blockDim.x + threadIdx.x;
    int n = g >> 5;
    if (n >= NN) return;
    int lane = g & 31;
    float4 xv = *(const float4*)&g_h1[(size_t)n * 128 + lane * 4];
    float4 wl = *(const float4*)&Wl[lane * 4];
    float4 wr = *(const float4*)&Wr[lane * 4];
    float s1 = xv.x * wl.x + xv.y * wl.y + xv.z * wl.z + xv.w * wl.w;
    float s2 = xv.x * wr.x + xv.y * wr.y + xv.z * wr.z + xv.w * wr.w;
#pragma unroll
    for (int o = 16; o > 0; o >>= 1) {
        s1 += __shfl_down_sync(0xffffffffu, s1, o);
        s2 += __shfl_down_sync(0xffffffffu, s2, o);
    }
    if (lane == 0) { g_s1[n] = s1; g_s2[n] = s2; }
}

__global__ void scatter_scalar(const int* __restrict__ ei, int E) {
    int e = blockIdx.x * blockDim.x + threadIdx.x;
    if (e < E) atomicAdd(&g_aggs[ei[E + e]], g_s1[ei[e]]);
}

__global__ void final_kernel(const float* __restrict__ bl, float* __restrict__ out) {
    int n = blockIdx.x * blockDim.x + threadIdx.x;
    if (n < NN) out[n] = g_aggs[n] / fmaxf(g_deg[n], 1.f) + bl[0] + g_s2[n];
}

// ---------------- concat: g_x[:,128:192] = x_cont ----------------
__global__ void copy_cont(const float* __restrict__ xc) {
    int i = blockIdx.x * blockDim.x + threadIdx.x;
    if (i < NN * 64) {
        int n = i >> 6, j = i & 63;
        g_x[(size_t)n * 192 + 128 + j] = xc[i];
    }
}

extern "C" void kernel_launch(void* const* d_in, const int* in_sizes, int n_in,
                              void* d_out, int out_size) {
    (void)n_in; (void)out_size;
    const int*   x_cat  = (const int*)  d_in[0];
    const float* x_cont = (const float*)d_in[1];
    const int*   ei     = (const int*)  d_in[2];
    const float* emb    = (const float*)d_in[3];
    const float* W1     = (const float*)d_in[4];
    const float* b1     = (const float*)d_in[5];
    const float* W2     = (const float*)d_in[6];
    const float* b2     = (const float*)d_in[7];
    const float* W3     = (const float*)d_in[8];
    const float* b3     = (const float*)d_in[9];
    const float* c1_Wl  = (const float*)d_in[10];
    const float* c1_bl  = (const float*)d_in[11];
    const float* c1_Wr  = (const float*)d_in[12];
    const float* c2_Wl  = (const float*)d_in[13];
    const float* c2_bl  = (const float*)d_in[14];
    const float* c2_Wr  = (const float*)d_in[15];
    const float* c3_Wl  = (const float*)d_in[16];
    const float* c3_bl  = (const float*)d_in[17];
    const float* c3_Wr  = (const float*)d_in[18];
    float* out = (float*)d_out;

    const int E = in_sizes[2] / 2;

    float *p_h1, *p_h2, *p_x, *p_y, *p_agg, *p_x2, *p_deg, *p_aggs;
    cudaGetSymbolAddress((void**)&p_h1,  g_h1);
    cudaGetSymbolAddress((void**)&p_h2,  g_h2);
    cudaGetSymbolAddress((void**)&p_x,   g_x);
    cudaGetSymbolAddress((void**)&p_y,   g_y);
    cudaGetSymbolAddress((void**)&p_agg, g_agg);
    cudaGetSymbolAddress((void**)&p_x2,  g_x2);
    cudaGetSymbolAddress((void**)&p_deg, g_deg);
    cudaGetSymbolAddress((void**)&p_aggs, g_aggs);

    const int GB = (NN + 127) / 128;

    // degree (independent of MLP)
    zero_kernel<<<128, 256>>>(p_deg, NN / 4);
    deg_kernel<<<(E + 255) / 256, 256>>>(ei, E);

    // MLP: gelu(emb@W1+b1) -> gelu(@W2+b2) -> @W3+b3 into g_x[:, :128]
    gemm_kernel<640, 1, 0><<<GB, 256>>>(nullptr, W1, b1, p_h1, 128, x_cat, emb);
    gemm_kernel<128, 0, 0><<<GB, 256>>>(p_h1, W2, b2, p_h2, 128, nullptr, nullptr);
    gemm_kernel<128, 0, 1><<<GB, 256>>>(p_h2, W3, b3, p_x, 192, nullptr, nullptr);
    copy_cont<<<(NN * 64 + 255) / 256, 256>>>(x_cont);

    // conv1: y = x@Wl; agg; x2 = gelu(agg/deg + bl + x@Wr)
    zero_kernel<<<2048, 256>>>(p_agg, NN * 128 / 4);
    gemm_kernel<192, 0, 1><<<GB, 256>>>(p_x, c1_Wl, nullptr, p_y, 128, nullptr, nullptr);
    scatter_vec<<<(E * 32 + 255) / 256, 256>>>(p_y, ei, E);
    gemm_kernel<192, 0, 2><<<GB, 256>>>(p_x, c1_Wr, c1_bl, p_x2, 128, nullptr, nullptr);

    // conv2
    zero_kernel<<<2048, 256>>>(p_agg, NN * 128 / 4);
    gemm_kernel<128, 0, 1><<<GB, 256>>>(p_x2, c2_Wl, nullptr, p_y, 128, nullptr, nullptr);
    scatter_vec<<<(E * 32 + 255) / 256, 256>>>(p_y, ei, E);
    gemm_kernel<128, 0, 2><<<GB, 256>>>(p_x2, c2_Wr, c2_bl, p_h1, 128, nullptr, nullptr);

    // conv3 (scalar): s1 = x@Wl, s2 = x@Wr; aggregate s1; combine
    conv3_dot<<<(NN * 32 + 255) / 256, 256>>>(c3_Wl, c3_Wr);
    zero_kernel<<<128, 256>>>(p_aggs, NN / 4);
    scatter_scalar<<<(E + 255) / 256, 256>>>(ei, E);
    final_kernel<<<(NN + 255) / 256, 256>>>(c3_bl, out);
}

// round 2
// speedup vs baseline: 1.4603x; 1.4603x over previous
#include <cuda_runtime.h>
#include <cstdint>
#include <math.h>

// Problem constants
#define NN   100000
#define NCAT 20
#define EMBD 32
#define CARD 100

// ---------------- scratch (device globals) ----------------
__device__ float g_h1[(size_t)NN * 128];
__device__ float g_h2[(size_t)NN * 128];
__device__ float g_x [(size_t)NN * 192];
__device__ float g_y [(size_t)NN * 128];
__device__ float g_agg[(size_t)NN * 128];
__device__ float g_x2[(size_t)NN * 128];
__device__ float g_deg[NN];
__device__ float g_s1[NN];
__device__ float g_s2[NN];
__device__ float g_aggs[NN];

__device__ __forceinline__ float gelu_f(float v) {
    return 0.5f * v * (1.0f + erff(v * 0.70710678118654752f));
}

// ---------------- tf32 helpers ----------------
__device__ __forceinline__ void split_tf32(float v, uint32_t& hi, uint32_t& lo) {
    asm("cvt.rna.tf32.f32 %0, %1;" : "=r"(hi) : "f"(v));
    float r = v - __uint_as_float(hi);
    asm("cvt.rna.tf32.f32 %0, %1;" : "=r"(lo) : "f"(r));
}

__device__ __forceinline__ void mma_tf32(float4& c, const uint32_t* a, const uint32_t* b) {
    asm volatile("mma.sync.aligned.m16n8k8.row.col.f32.tf32.tf32.f32 "
                 "{%0,%1,%2,%3}, {%4,%5,%6,%7}, {%8,%9}, {%0,%1,%2,%3};"
                 : "+f"(c.x), "+f"(c.y), "+f"(c.z), "+f"(c.w)
                 : "r"(a[0]), "r"(a[1]), "r"(a[2]), "r"(a[3]), "r"(b[0]), "r"(b[1]));
}

__device__ __forceinline__ void cpasync16(uint32_t dst, const void* src, int srcsz) {
    asm volatile("cp.async.cg.shared.global [%0], [%1], 16, %2;"
                 :: "r"(dst), "l"(src), "r"(srcsz));
}
__device__ __forceinline__ void cp_commit() { asm volatile("cp.async.commit_group;"); }
template<int N> __device__ __forceinline__ void cp_wait() {
    asm volatile("cp.async.wait_group %0;" :: "n"(N));
}

// ---------------- zero kernel ----------------
__global__ void zero_kernel(float* __restrict__ p, int n4) {
    int i = blockIdx.x * blockDim.x + threadIdx.x;
    int stride = gridDim.x * blockDim.x;
    float4* p4 = (float4*)p;
    float4 z = make_float4(0.f, 0.f, 0.f, 0.f);
    for (; i < n4; i += stride) p4[i] = z;
}

// ---------------- tf32 tensor-core GEMM: C[M x 128] = A[M x K] @ W[K x 128] ----------------
// 3xTF32: hi*hi + hi*lo + lo*hi for fp32-class accuracy.
// Block tile 128x128, kstep 16, 8 warps as 2(M) x 4(N), warp tile 64x32.
// INMODE: 0 = A[m*lda + k], 1 = embedding gather
// EPI: 0 = gelu(acc+bias); 1 = acc+bias (bias may be null); 2 = gelu(acc+bias+agg/deg)
#define LDK 20
#define LDN 136
#define A_ELE (128 * LDK)
#define B_ELE (16 * LDN)

template<int K, int INMODE, int EPI>
__global__ __launch_bounds__(256)
void tgemm(const float* __restrict__ A, int lda,
           const float* __restrict__ W,
           const float* __restrict__ bias,
           float* __restrict__ C, int ldc,
           const int* __restrict__ xcat,
           const float* __restrict__ emb)
{
    __shared__ __align__(16) float As[2][A_ELE];
    __shared__ __align__(16) float Bs[2][B_ELE];

    const int tid  = threadIdx.x;
    const int m0   = blockIdx.x * 128;
    const int wid  = tid >> 5;
    const int lane = tid & 31;
    const int g    = lane >> 2;   // 0..7
    const int tig  = lane & 3;    // 0..3
    const int warpM = (wid >> 2) * 64;
    const int warpN = (wid & 3) * 32;

    constexpr int NK = K / 16;

    float4 acc[4][4];
#pragma unroll
    for (int i = 0; i < 4; i++)
#pragma unroll
        for (int j = 0; j < 4; j++) acc[i][j] = make_float4(0.f, 0.f, 0.f, 0.f);

    // copy one k-step tile into stage buf
    auto copy_tile = [&](int buf, int k0) {
        uint32_t aBase = (uint32_t)__cvta_generic_to_shared(&As[buf][0]);
        uint32_t bBase = (uint32_t)__cvta_generic_to_shared(&Bs[buf][0]);
        // A tile: 128 rows x 16 k  (512 float4, 2 per thread)
#pragma unroll
        for (int i = 0; i < 2; i++) {
            int flat = tid + i * 256;
            int r = flat >> 2, seg = flat & 3;
            int gm = m0 + r;
            const float* src;
            int sz = 16;
            if (INMODE == 1) {
                int c = k0 >> 5;
                int cat = (gm < NN) ? xcat[gm * NCAT + c] : 0;
                src = &emb[(size_t)(c * CARD + cat) * EMBD + (k0 & 31) + seg * 4];
            } else {
                src = &A[(size_t)(gm < NN ? gm : 0) * lda + k0 + seg * 4];
            }
            if (gm >= NN) sz = 0;
            cpasync16(aBase + (uint32_t)(r * LDK + seg * 4) * 4, src, sz);
        }
        // B tile: 16 k x 128 n (512 float4, 2 per thread)
#pragma unroll
        for (int i = 0; i < 2; i++) {
            int flat = tid + i * 256;
            int k = flat >> 5, n0 = (flat & 31) * 4;
            cpasync16(bBase + (uint32_t)(k * LDN + n0) * 4,
                      &W[(size_t)(k0 + k) * 128 + n0], 16);
        }
    };

    copy_tile(0, 0);
    cp_commit();

    for (int ks = 0; ks < NK; ks++) {
        if (ks + 1 < NK) {
            copy_tile((ks + 1) & 1, (ks + 1) * 16);
            cp_commit();
            cp_wait<1>();
        } else {
            cp_wait<0>();
        }
        __syncthreads();

        const int buf = ks & 1;
#pragma unroll
        for (int kc = 0; kc < 16; kc += 8) {
            // B fragments for the 4 n-tiles
            uint32_t bh[4][2], bl[4][2];
#pragma unroll
            for (int nt = 0; nt < 4; nt++) {
                int cb = warpN + nt * 8 + g;
                float b0 = Bs[buf][(kc + tig) * LDN + cb];
                float b1 = Bs[buf][(kc + tig + 4) * LDN + cb];
                split_tf32(b0, bh[nt][0], bl[nt][0]);
                split_tf32(b1, bh[nt][1], bl[nt][1]);
            }
#pragma unroll
            for (int mt = 0; mt < 4; mt++) {
                int rm = warpM + mt * 16 + g;
                float a0 = As[buf][rm * LDK + kc + tig];
                float a1 = As[buf][(rm + 8) * LDK + kc + tig];
                float a2 = As[buf][rm * LDK + kc + tig + 4];
                float a3 = As[buf][(rm + 8) * LDK + kc + tig + 4];
                uint32_t ah[4], al[4];
                split_tf32(a0, ah[0], al[0]);
                split_tf32(a1, ah[1], al[1]);
                split_tf32(a2, ah[2], al[2]);
                split_tf32(a3, ah[3], al[3]);
#pragma unroll
                for (int nt = 0; nt < 4; nt++) {
                    mma_tf32(acc[mt][nt], ah, bh[nt]);
                    mma_tf32(acc[mt][nt], ah, bl[nt]);
                    mma_tf32(acc[mt][nt], al, bh[nt]);
                }
            }
        }
        __syncthreads();
    }

    // epilogue
#pragma unroll
    for (int mt = 0; mt < 4; mt++) {
        int r0 = m0 + warpM + mt * 16 + g;
#pragma unroll
        for (int rr = 0; rr < 2; rr++) {
            int r = r0 + rr * 8;
            if (r >= NN) continue;
            float inv = 1.f;
            if (EPI == 2) inv = 1.f / fmaxf(g_deg[r], 1.f);
#pragma unroll
            for (int nt = 0; nt < 4; nt++) {
                int col = warpN + nt * 8 + tig * 2;
                float v0 = (rr == 0) ? acc[mt][nt].x : acc[mt][nt].z;
                float v1 = (rr == 0) ? acc[mt][nt].y : acc[mt][nt].w;
                if (bias) { v0 += bias[col]; v1 += bias[col + 1]; }
                if (EPI == 2) {
                    v0 += g_agg[(size_t)r * 128 + col] * inv;
                    v1 += g_agg[(size_t)r * 128 + col + 1] * inv;
                }
                if (EPI == 0 || EPI == 2) { v0 = gelu_f(v0); v1 = gelu_f(v1); }
                float2 o = make_float2(v0, v1);
                *(float2*)&C[(size_t)r * ldc + col] = o;
            }
        }
    }
}

// ---------------- degree computation ----------------
__global__ void deg_kernel(const int* __restrict__ ei, int E) {
    int e = blockIdx.x * blockDim.x + threadIdx.x;
    if (e < E) atomicAdd(&g_deg[ei[E + e]], 1.0f);
}

// ---------------- 128-wide edge scatter ----------------
__global__ void scatter_vec(const float* __restrict__ y, const int* __restrict__ ei, int E) {
    int gidx = blockIdx.x * blockDim.x + threadIdx.x;
    int e = gidx >> 5;
    if (e >= E) return;
    int lane = gidx & 31;
    int src = __ldg(&ei[e]);
    int dst = __ldg(&ei[E + e]);
    float4 v = *(const float4*)&y[(size_t)src * 128 + lane * 4];
    float* p = &g_agg[(size_t)dst * 128 + lane * 4];
    asm volatile("red.global.add.v4.f32 [%0], {%1,%2,%3,%4};"
                 :: "l"(p), "f"(v.x), "f"(v.y), "f"(v.z), "f"(v.w) : "memory");
}

// ---------------- conv3 ----------------
__global__ void conv3_dot(const float* __restrict__ Wl, const float* __restrict__ Wr) {
    int gidx = blockIdx.x * blockDim.x + threadIdx.x;
    int n = gidx >> 5;
    if (n >= NN) return;
    int lane = gidx & 31;
    float4 xv = *(const float4*)&g_h1[(size_t)n * 128 + lane * 4];
    float4 wl = *(const float4*)&Wl[lane * 4];
    float4 wr = *(const float4*)&Wr[lane * 4];
    float s1 = xv.x * wl.x + xv.y * wl.y + xv.z * wl.z + xv.w * wl.w;
    float s2 = xv.x * wr.x + xv.y * wr.y + xv.z * wr.z + xv.w * wr.w;
#pragma unroll
    for (int o = 16; o > 0; o >>= 1) {
        s1 += __shfl_down_sync(0xffffffffu, s1, o);
        s2 += __shfl_down_sync(0xffffffffu, s2, o);
    }
    if (lane == 0) { g_s1[n] = s1; g_s2[n] = s2; }
}

__global__ void scatter_scalar(const int* __restrict__ ei, int E) {
    int e = blockIdx.x * blockDim.x + threadIdx.x;
    if (e < E) atomicAdd(&g_aggs[ei[E + e]], g_s1[ei[e]]);
}

__global__ void final_kernel(const float* __restrict__ bl, float* __restrict__ out) {
    int n = blockIdx.x * blockDim.x + threadIdx.x;
    if (n < NN) out[n] = g_aggs[n] / fmaxf(g_deg[n], 1.f) + bl[0] + g_s2[n];
}

// ---------------- concat: g_x[:,128:192] = x_cont ----------------
__global__ void copy_cont(const float* __restrict__ xc) {
    int i = blockIdx.x * blockDim.x + threadIdx.x;
    if (i < NN * 16) {
        int n = i >> 4, j = (i & 15) * 4;
        *(float4*)&g_x[(size_t)n * 192 + 128 + j] = *(const float4*)&xc[n * 64 + j];
    }
}

extern "C" void kernel_launch(void* const* d_in, const int* in_sizes, int n_in,
                              void* d_out, int out_size) {
    (void)n_in; (void)out_size;
    const int*   x_cat  = (const int*)  d_in[0];
    const float* x_cont = (const float*)d_in[1];
    const int*   ei     = (const int*)  d_in[2];
    const float* emb    = (const float*)d_in[3];
    const float* W1     = (const float*)d_in[4];
    const float* b1     = (const float*)d_in[5];
    const float* W2     = (const float*)d_in[6];
    const float* b2     = (const float*)d_in[7];
    const float* W3     = (const float*)d_in[8];
    const float* b3     = (const float*)d_in[9];
    const float* c1_Wl  = (const float*)d_in[10];
    const float* c1_bl  = (const float*)d_in[11];
    const float* c1_Wr  = (const float*)d_in[12];
    const float* c2_Wl  = (const float*)d_in[13];
    const float* c2_bl  = (const float*)d_in[14];
    const float* c2_Wr  = (const float*)d_in[15];
    const float* c3_Wl  = (const float*)d_in[16];
    const float* c3_bl  = (const float*)d_in[17];
    const float* c3_Wr  = (const float*)d_in[18];
    float* out = (float*)d_out;

    const int E = in_sizes[2] / 2;

    float *p_h1, *p_h2, *p_x, *p_y, *p_agg, *p_x2, *p_deg, *p_aggs;
    cudaGetSymbolAddress((void**)&p_h1,  g_h1);
    cudaGetSymbolAddress((void**)&p_h2,  g_h2);
    cudaGetSymbolAddress((void**)&p_x,   g_x);
    cudaGetSymbolAddress((void**)&p_y,   g_y);
    cudaGetSymbolAddress((void**)&p_agg, g_agg);
    cudaGetSymbolAddress((void**)&p_x2,  g_x2);
    cudaGetSymbolAddress((void**)&p_deg, g_deg);
    cudaGetSymbolAddress((void**)&p_aggs, g_aggs);

    const int GB = (NN + 127) / 128;

    // degree (independent of MLP)
    zero_kernel<<<128, 256>>>(p_deg, NN / 4);
    deg_kernel<<<(E + 255) / 256, 256>>>(ei, E);

    // MLP
    tgemm<640, 1, 0><<<GB, 256>>>(nullptr, 0, W1, b1, p_h1, 128, x_cat, emb);
    tgemm<128, 0, 0><<<GB, 256>>>(p_h1, 128, W2, b2, p_h2, 128, nullptr, nullptr);
    tgemm<128, 0, 1><<<GB, 256>>>(p_h2, 128, W3, b3, p_x, 192, nullptr, nullptr);
    copy_cont<<<(NN * 16 + 255) / 256, 256>>>(x_cont);

    // conv1
    zero_kernel<<<2048, 256>>>(p_agg, NN * 128 / 4);
    tgemm<192, 0, 1><<<GB, 256>>>(p_x, 192, c1_Wl, nullptr, p_y, 128, nullptr, nullptr);
    scatter_vec<<<(E * 32 + 255) / 256, 256>>>(p_y, ei, E);
    tgemm<192, 0, 2><<<GB, 256>>>(p_x, 192, c1_Wr, c1_bl, p_x2, 128, nullptr, nullptr);

    // conv2
    zero_kernel<<<2048, 256>>>(p_agg, NN * 128 / 4);
    tgemm<128, 0, 1><<<GB, 256>>>(p_x2, 128, c2_Wl, nullptr, p_y, 128, nullptr, nullptr);
    scatter_vec<<<(E * 32 + 255) / 256, 256>>>(p_y, ei, E);
    tgemm<128, 0, 2><<<GB, 256>>>(p_x2, 128, c2_Wr, c2_bl, p_h1, 128, nullptr, nullptr);

    // conv3 (scalar)
    conv3_dot<<<(NN * 32 + 255) / 256, 256>>>(c3_Wl, c3_Wr);
    zero_kernel<<<128, 256>>>(p_aggs, NN / 4);
    scatter_scalar<<<(E + 255) / 256, 256>>>(ei, E);
    final_kernel<<<(NN + 255) / 256, 256>>>(c3_bl, out);
}